// round 2
// baseline (speedup 1.0000x reference)
#include <cuda_runtime.h>

#define NB_B   4096
#define NB_S   128
#define NB_D   9
#define NB_V   5
#define NB_BLK 4
#define RP     12   // padded row stride (floats) for 16B-aligned float4 loads

// dot of 9-float row (16B-aligned, padded to 12) with register vector x[9]
__device__ __forceinline__ float dot9(const float* __restrict__ row, const float x[NB_D]) {
    float4 a = *(const float4*)(row);
    float4 b = *(const float4*)(row + 4);
    float  c = row[8];
    float s = a.x * x[0];
    s = fmaf(a.y, x[1], s);
    s = fmaf(a.z, x[2], s);
    s = fmaf(a.w, x[3], s);
    s = fmaf(b.x, x[4], s);
    s = fmaf(b.y, x[5], s);
    s = fmaf(b.z, x[6], s);
    s = fmaf(b.w, x[7], s);
    s = fmaf(c,   x[8], s);
    return s;
}

__global__ __launch_bounds__(NB_S)
void bert_kernel(const int*   __restrict__ tokens,
                 const float* __restrict__ emb,
                 const float* __restrict__ Wq, const float* __restrict__ bq,
                 const float* __restrict__ Wk, const float* __restrict__ bk,
                 const float* __restrict__ Wv, const float* __restrict__ bv,
                 const float* __restrict__ Wout, const float* __restrict__ bout,
                 float* __restrict__ out)
{
    __shared__ __align__(16) float sW[NB_BLK][3][NB_D][RP];   // [blk][q/k/v][row e][d]
    __shared__ __align__(16) float sBias[NB_BLK][3][RP];
    __shared__ __align__(16) float sWout[NB_V][RP];
    __shared__ __align__(16) float sEmb[NB_V][RP];
    __shared__ float sBout[NB_V];
    __shared__ __align__(16) float sK[NB_S][RP];
    __shared__ __align__(16) float sV[NB_S][RP];

    const int tid = threadIdx.x;
    const int b   = blockIdx.x;

    // ---- cooperative load of all weights into smem (one-time, L2-broadcast) ----
    for (int idx = tid; idx < NB_BLK * NB_D * NB_D; idx += NB_S) {
        int i = idx / (NB_D * NB_D);
        int r = idx % (NB_D * NB_D);
        int e = r / NB_D, d = r % NB_D;
        sW[i][0][e][d] = Wq[idx];
        sW[i][1][e][d] = Wk[idx];
        sW[i][2][e][d] = Wv[idx];
    }
    for (int idx = tid; idx < NB_BLK * NB_D; idx += NB_S) {
        int i = idx / NB_D, e = idx % NB_D;
        sBias[i][0][e] = bq[idx];
        sBias[i][1][e] = bk[idx];
        sBias[i][2][e] = bv[idx];
    }
    if (tid < NB_V * NB_D) {
        sWout[tid / NB_D][tid % NB_D] = Wout[tid];
        sEmb [tid / NB_D][tid % NB_D] = emb[tid];
    }
    if (tid < NB_V) sBout[tid] = bout[tid];

    const int tok = tokens[b * NB_S + tid];

    __syncthreads();

    // ---- x = emb[token] + positional encoding (thread tid == seq position) ----
    float x[NB_D];
    {
        const float fs = (float)tid;
        // exponents (2*(d//2))/9 for d pairs; inv_freq = 10000^{-exp} = exp2(-exp*log2(1e4))
        const float L2_1E4 = 13.287712379549449f;
        #pragma unroll
        for (int d = 0; d < NB_D; ++d) {
            float ex   = (float)(2 * (d >> 1)) * (1.0f / 9.0f);
            float invf = exp2f(-ex * L2_1E4);
            float ang  = fs * invf;
            float pe   = ((d & 1) == 0) ? sinf(ang) : cosf(ang);
            x[d] = sEmb[tok][d] + pe;
        }
    }

    const float scale = 1.0f / 3.0f;   // 1/sqrt(9)

    // ---- 4 attention blocks ----
    for (int blk = 0; blk < NB_BLK; ++blk) {
        float q[NB_D];
        {
            float kk[NB_D], vv[NB_D];
            #pragma unroll
            for (int e = 0; e < NB_D; ++e) {
                q[e]  = sBias[blk][0][e] + dot9(&sW[blk][0][e][0], x);
                kk[e] = sBias[blk][1][e] + dot9(&sW[blk][1][e][0], x);
                vv[e] = sBias[blk][2][e] + dot9(&sW[blk][2][e][0], x);
            }
            float4* kp = (float4*)&sK[tid][0];
            kp[0] = make_float4(kk[0], kk[1], kk[2], kk[3]);
            kp[1] = make_float4(kk[4], kk[5], kk[6], kk[7]);
            kp[2] = make_float4(kk[8], 0.f, 0.f, 0.f);
            float4* vp = (float4*)&sV[tid][0];
            vp[0] = make_float4(vv[0], vv[1], vv[2], vv[3]);
            vp[1] = make_float4(vv[4], vv[5], vv[6], vv[7]);
            vp[2] = make_float4(vv[8], 0.f, 0.f, 0.f);
        }
        __syncthreads();

        // pass 1: row max of scores (unscaled dots; scale applied to the max)
        float m = -1e30f;
        #pragma unroll 4
        for (int k = 0; k < NB_S; ++k) {
            float sc = dot9(&sK[k][0], q);
            m = fmaxf(m, sc);
        }
        m *= scale;

        // pass 2: exp-weighted accumulation of V
        float den = 0.f;
        float acc[NB_D];
        #pragma unroll
        for (int d = 0; d < NB_D; ++d) acc[d] = 0.f;

        #pragma unroll 2
        for (int k = 0; k < NB_S; ++k) {
            float sc = dot9(&sK[k][0], q) * scale;
            float e  = __expf(sc - m);
            den += e;
            const float* vr = &sV[k][0];
            float4 v0 = *(const float4*)(vr);
            float4 v1 = *(const float4*)(vr + 4);
            float  v8 = vr[8];
            acc[0] = fmaf(e, v0.x, acc[0]);
            acc[1] = fmaf(e, v0.y, acc[1]);
            acc[2] = fmaf(e, v0.z, acc[2]);
            acc[3] = fmaf(e, v0.w, acc[3]);
            acc[4] = fmaf(e, v1.x, acc[4]);
            acc[5] = fmaf(e, v1.y, acc[5]);
            acc[6] = fmaf(e, v1.z, acc[6]);
            acc[7] = fmaf(e, v1.w, acc[7]);
            acc[8] = fmaf(e, v8,   acc[8]);
        }
        float inv = 1.0f / den;
        #pragma unroll
        for (int d = 0; d < NB_D; ++d) x[d] = acc[d] * inv;

        __syncthreads();   // protect sK/sV before next block overwrites
    }

    // ---- output head: logits + log_softmax over V=5 ----
    float lg[NB_V];
    #pragma unroll
    for (int v = 0; v < NB_V; ++v)
        lg[v] = sBout[v] + dot9(&sWout[v][0], x);

    float mx = lg[0];
    #pragma unroll
    for (int v = 1; v < NB_V; ++v) mx = fmaxf(mx, lg[v]);
    float sum = 0.f;
    #pragma unroll
    for (int v = 0; v < NB_V; ++v) sum += __expf(lg[v] - mx);
    float lse = mx + logf(sum);

    float* o = out + ((size_t)b * NB_S + tid) * NB_V;
    #pragma unroll
    for (int v = 0; v < NB_V; ++v) o[v] = lg[v] - lse;
}

extern "C" void kernel_launch(void* const* d_in, const int* in_sizes, int n_in,
                              void* d_out, int out_size)
{
    const int*   tokens = (const int*)  d_in[0];
    const float* emb    = (const float*)d_in[1];
    const float* Wq     = (const float*)d_in[2];
    const float* bq     = (const float*)d_in[3];
    const float* Wk     = (const float*)d_in[4];
    const float* bk     = (const float*)d_in[5];
    const float* Wv     = (const float*)d_in[6];
    const float* bv     = (const float*)d_in[7];
    const float* Wout   = (const float*)d_in[8];
    const float* bout   = (const float*)d_in[9];
    float* out = (float*)d_out;

    bert_kernel<<<NB_B, NB_S>>>(tokens, emb, Wq, bq, Wk, bk, Wv, bv, Wout, bout, out);
}

// round 3
// speedup vs baseline: 1.2174x; 1.2174x over previous
#include <cuda_runtime.h>

typedef unsigned long long ull;

#define NB_B   4096
#define NB_S   128
#define NB_D   9
#define NB_V   5
#define NB_BLK 4
#define KVST   10    // ull (float2) per K/V row: 80B, 16B-aligned

// ---------- packed f32x2 helpers (Blackwell sm_103a) ----------
__device__ __forceinline__ ull pack2(float a, float b) {
    ull r; asm("mov.b64 %0, {%1,%2};" : "=l"(r) : "f"(a), "f"(b)); return r;
}
__device__ __forceinline__ void unpack2(ull v, float& a, float& b) {
    asm("mov.b64 {%0,%1}, %2;" : "=f"(a), "=f"(b) : "l"(v));
}
__device__ __forceinline__ ull fma2(ull a, ull b, ull c) {
    ull d; asm("fma.rn.f32x2 %0, %1, %2, %3;" : "=l"(d) : "l"(a), "l"(b), "l"(c)); return d;
}
__device__ __forceinline__ ull mul2(ull a, ull b) {
    ull d; asm("mul.rn.f32x2 %0, %1, %2;" : "=l"(d) : "l"(a), "l"(b)); return d;
}
__device__ __forceinline__ ull add2(ull a, ull b) {
    ull d; asm("add.rn.f32x2 %0, %1, %2;" : "=l"(d) : "l"(a), "l"(b)); return d;
}

// load a duplicated 9-element f32x2 row (16B-aligned, stride KVST)
__device__ __forceinline__ void ldrow(const ull* __restrict__ p, ull r[NB_D]) {
    ulonglong2 a = *(const ulonglong2*)(p);
    ulonglong2 b = *(const ulonglong2*)(p + 2);
    ulonglong2 c = *(const ulonglong2*)(p + 4);
    ulonglong2 d = *(const ulonglong2*)(p + 6);
    r[0]=a.x; r[1]=a.y; r[2]=b.x; r[3]=b.y;
    r[4]=c.x; r[5]=c.y; r[6]=d.x; r[7]=d.y; r[8]=p[8];
}

// packed dot: two 4/5-deep chains for ILP, 2 dots per call (one per f32x2 half)
__device__ __forceinline__ ull dot9p(const ull r[NB_D], const ull q[NB_D]) {
    ull u = mul2(r[0], q[0]);
    u = fma2(r[1], q[1], u);
    u = fma2(r[2], q[2], u);
    u = fma2(r[3], q[3], u);
    ull v = mul2(r[4], q[4]);
    v = fma2(r[5], q[5], v);
    v = fma2(r[6], q[6], v);
    v = fma2(r[7], q[7], v);
    v = fma2(r[8], q[8], v);
    return add2(u, v);
}

// scalar-weight row projected against two packed-x pairs (weights duplicated on the fly)
__device__ __forceinline__ void proj(const float* __restrict__ wrow, float bias,
                                     const ull x0[NB_D], const ull x1[NB_D],
                                     ull& o0, ull& o1) {
    float4 a = *(const float4*)(wrow);
    float4 b = *(const float4*)(wrow + 4);
    float  c = wrow[8];
    ull w[NB_D];
    w[0]=pack2(a.x,a.x); w[1]=pack2(a.y,a.y); w[2]=pack2(a.z,a.z); w[3]=pack2(a.w,a.w);
    w[4]=pack2(b.x,b.x); w[5]=pack2(b.y,b.y); w[6]=pack2(b.z,b.z); w[7]=pack2(b.w,b.w);
    w[8]=pack2(c,c);
    ull t0 = pack2(bias, bias);
    ull t1 = t0;
    #pragma unroll
    for (int d = 0; d < NB_D; ++d) {
        t0 = fma2(w[d], x0[d], t0);
        t1 = fma2(w[d], x1[d], t1);
    }
    o0 = t0; o1 = t1;
}

__global__ __launch_bounds__(64)
void bert_kernel(const int*   __restrict__ tokens,
                 const float* __restrict__ emb,
                 const float* __restrict__ Wq, const float* __restrict__ bq,
                 const float* __restrict__ Wk, const float* __restrict__ bk,
                 const float* __restrict__ Wv, const float* __restrict__ bv,
                 const float* __restrict__ Wout, const float* __restrict__ bout,
                 float* __restrict__ out)
{
    // duplicated (hot) K/V tiles: one batch per warp
    __shared__ __align__(16) ull sK[2][NB_S][KVST];     // 20480 B
    __shared__ __align__(16) ull sV[2][NB_S][KVST];     // 20480 B
    // scalar (cold) weights
    __shared__ __align__(16) float sW[NB_BLK][3][NB_D][12];  // 5184 B
    __shared__ float sB[NB_BLK][3][NB_D];                    // 432 B
    __shared__ __align__(16) float sWout[NB_V][12];          // 240 B
    __shared__ __align__(16) float sEmb[NB_V][12];           // 240 B
    __shared__ float sBout[NB_V];
    // total ~47.1 KB

    const int tid  = threadIdx.x;
    const int w    = tid >> 5;       // warp id == batch-in-CTA
    const int lane = tid & 31;
    const int b    = blockIdx.x * 2 + w;

    // ---- cooperative weight load ----
    for (int idx = tid; idx < NB_BLK * NB_D * NB_D; idx += 64) {
        int i = idx / (NB_D * NB_D);
        int r = idx % (NB_D * NB_D);
        int e = r / NB_D, d = r % NB_D;
        sW[i][0][e][d] = Wq[idx];
        sW[i][1][e][d] = Wk[idx];
        sW[i][2][e][d] = Wv[idx];
    }
    for (int idx = tid; idx < NB_BLK * NB_D; idx += 64) {
        int i = idx / NB_D, e = idx % NB_D;
        sB[i][0][e] = bq[idx];
        sB[i][1][e] = bk[idx];
        sB[i][2][e] = bv[idx];
    }
    if (tid < NB_V * NB_D) {
        sWout[tid / NB_D][tid % NB_D] = Wout[tid];
        sEmb [tid / NB_D][tid % NB_D] = emb[tid];
    }
    if (tid < NB_V) sBout[tid] = bout[tid];
    __syncthreads();

    // ---- x for 4 positions per lane, packed into 2 f32x2 pairs ----
    // pair0 = (lane, lane+32), pair1 = (lane+64, lane+96)
    ull x2[2][NB_D];
    {
        const float L2_1E4 = 13.287712379549449f;
        #pragma unroll
        for (int p = 0; p < 2; ++p) {
            int posA = lane + p * 64;
            int posB = posA + 32;
            int tokA = tokens[b * NB_S + posA];
            int tokB = tokens[b * NB_S + posB];
            #pragma unroll
            for (int d = 0; d < NB_D; ++d) {
                float ex   = (float)(2 * (d >> 1)) * (1.0f / 9.0f);
                float invf = exp2f(-ex * L2_1E4);
                float angA = (float)posA * invf;
                float angB = (float)posB * invf;
                float peA  = ((d & 1) == 0) ? sinf(angA) : cosf(angA);
                float peB  = ((d & 1) == 0) ? sinf(angB) : cosf(angB);
                x2[p][d] = pack2(sEmb[tokA][d] + peA, sEmb[tokB][d] + peB);
            }
        }
    }

    const float scale = 1.0f / 3.0f;

    for (int blk = 0; blk < NB_BLK; ++blk) {
        // ---- QKV projection (packed over query pairs) ----
        ull q2[2][NB_D];
        #pragma unroll
        for (int e = 0; e < NB_D; ++e) {
            ull k0, k1, v0, v1;
            proj(&sW[blk][0][e][0], sB[blk][0][e], x2[0], x2[1], q2[0][e], q2[1][e]);
            proj(&sW[blk][1][e][0], sB[blk][1][e], x2[0], x2[1], k0, k1);
            proj(&sW[blk][2][e][0], sB[blk][2][e], x2[0], x2[1], v0, v1);
            float a, bb;
            unpack2(k0, a, bb);
            sK[w][lane     ][e] = pack2(a, a);
            sK[w][lane + 32][e] = pack2(bb, bb);
            unpack2(k1, a, bb);
            sK[w][lane + 64][e] = pack2(a, a);
            sK[w][lane + 96][e] = pack2(bb, bb);
            unpack2(v0, a, bb);
            sV[w][lane     ][e] = pack2(a, a);
            sV[w][lane + 32][e] = pack2(bb, bb);
            unpack2(v1, a, bb);
            sV[w][lane + 64][e] = pack2(a, a);
            sV[w][lane + 96][e] = pack2(bb, bb);
        }
        __syncwarp();

        // ---- pass 1: row max of scores (4 queries per lane) ----
        float m0 = -1e30f, m1 = -1e30f, m2 = -1e30f, m3 = -1e30f;
        #pragma unroll 2
        for (int k = 0; k < NB_S; ++k) {
            ull kr[NB_D];
            ldrow(&sK[w][k][0], kr);
            ull d0 = dot9p(kr, q2[0]);
            ull d1 = dot9p(kr, q2[1]);
            float sa, sb, sc, sd;
            unpack2(d0, sa, sb);
            unpack2(d1, sc, sd);
            m0 = fmaxf(m0, sa); m1 = fmaxf(m1, sb);
            m2 = fmaxf(m2, sc); m3 = fmaxf(m3, sd);
        }
        m0 *= scale; m1 *= scale; m2 *= scale; m3 *= scale;

        // ---- pass 2: exp-weighted V accumulation ----
        ull acc0[NB_D], acc1[NB_D];
        #pragma unroll
        for (int d = 0; d < NB_D; ++d) { acc0[d] = 0ULL; acc1[d] = 0ULL; }
        float den0 = 0.f, den1 = 0.f, den2 = 0.f, den3 = 0.f;

        #pragma unroll 2
        for (int k = 0; k < NB_S; ++k) {
            ull kr[NB_D];
            ldrow(&sK[w][k][0], kr);
            ull d0 = dot9p(kr, q2[0]);
            ull d1 = dot9p(kr, q2[1]);
            float sa, sb, sc, sd;
            unpack2(d0, sa, sb);
            unpack2(d1, sc, sd);
            float e0 = __expf(fmaf(sa, scale, -m0));
            float e1 = __expf(fmaf(sb, scale, -m1));
            float e2 = __expf(fmaf(sc, scale, -m2));
            float e3 = __expf(fmaf(sd, scale, -m3));
            den0 += e0; den1 += e1; den2 += e2; den3 += e3;
            ull ep0 = pack2(e0, e1);
            ull ep1 = pack2(e2, e3);
            ull vr[NB_D];
            ldrow(&sV[w][k][0], vr);
            #pragma unroll
            for (int d = 0; d < NB_D; ++d) {
                acc0[d] = fma2(ep0, vr[d], acc0[d]);
                acc1[d] = fma2(ep1, vr[d], acc1[d]);
            }
        }
        ull inv0 = pack2(__fdividef(1.f, den0), __fdividef(1.f, den1));
        ull inv1 = pack2(__fdividef(1.f, den2), __fdividef(1.f, den3));
        #pragma unroll
        for (int d = 0; d < NB_D; ++d) {
            x2[0][d] = mul2(acc0[d], inv0);
            x2[1][d] = mul2(acc1[d], inv1);
        }
        __syncwarp();   // protect sK/sV before next block overwrites
    }

    // ---- output head: logits + log_softmax over V=5 (packed logits) ----
    ull lg0[NB_V], lg1[NB_V];
    #pragma unroll
    for (int v = 0; v < NB_V; ++v)
        proj(&sWout[v][0], sBout[v], x2[0], x2[1], lg0[v], lg1[v]);

    #pragma unroll
    for (int p = 0; p < 2; ++p) {
        #pragma unroll
        for (int half = 0; half < 2; ++half) {
            int pos = lane + p * 64 + half * 32;
            float lg[NB_V];
            #pragma unroll
            for (int v = 0; v < NB_V; ++v) {
                float a, bb;
                unpack2(p == 0 ? lg0[v] : lg1[v], a, bb);
                lg[v] = half == 0 ? a : bb;
            }
            float mx = lg[0];
            #pragma unroll
            for (int v = 1; v < NB_V; ++v) mx = fmaxf(mx, lg[v]);
            float sum = 0.f;
            #pragma unroll
            for (int v = 0; v < NB_V; ++v) sum += __expf(lg[v] - mx);
            float lse = mx + __logf(sum);
            float* o = out + ((size_t)b * NB_S + pos) * NB_V;
            #pragma unroll
            for (int v = 0; v < NB_V; ++v) o[v] = lg[v] - lse;
        }
    }
}

extern "C" void kernel_launch(void* const* d_in, const int* in_sizes, int n_in,
                              void* d_out, int out_size)
{
    const int*   tokens = (const int*)  d_in[0];
    const float* emb    = (const float*)d_in[1];
    const float* Wq     = (const float*)d_in[2];
    const float* bq     = (const float*)d_in[3];
    const float* Wk     = (const float*)d_in[4];
    const float* bk     = (const float*)d_in[5];
    const float* Wv     = (const float*)d_in[6];
    const float* bv     = (const float*)d_in[7];
    const float* Wout   = (const float*)d_in[8];
    const float* bout   = (const float*)d_in[9];
    float* outp = (float*)d_out;

    bert_kernel<<<NB_B / 2, 64>>>(tokens, emb, Wq, bq, Wk, bk, Wv, bv, Wout, bout, outp);
}

// round 4
// speedup vs baseline: 1.4058x; 1.1547x over previous
#include <cuda_runtime.h>

typedef unsigned long long ull;

#define NB_B   4096
#define NB_S   128
#define NB_D   9
#define NB_V   5
#define NB_BLK 4
#define RP     12   // padded weight-row stride (floats)

// log2(e)/3 : folds softmax scale (1/sqrt(9)) and exp->exp2 conversion into Wq/bq
#define QSCL   0.48089834696298784f

// ---------- packed f32x2 helpers (Blackwell sm_103a) ----------
__device__ __forceinline__ ull pack2(float a, float b) {
    ull r; asm("mov.b64 %0, {%1,%2};" : "=l"(r) : "f"(a), "f"(b)); return r;
}
__device__ __forceinline__ void unpack2(ull v, float& a, float& b) {
    asm("mov.b64 {%0,%1}, %2;" : "=f"(a), "=f"(b) : "l"(v));
}
__device__ __forceinline__ ull fma2(ull a, ull b, ull c) {
    ull d; asm("fma.rn.f32x2 %0, %1, %2, %3;" : "=l"(d) : "l"(a), "l"(b), "l"(c)); return d;
}
__device__ __forceinline__ ull mul2(ull a, ull b) {
    ull d; asm("mul.rn.f32x2 %0, %1, %2;" : "=l"(d) : "l"(a), "l"(b)); return d;
}
__device__ __forceinline__ ull add2(ull a, ull b) {
    ull d; asm("add.rn.f32x2 %0, %1, %2;" : "=l"(d) : "l"(a), "l"(b)); return d;
}
__device__ __forceinline__ float ex2f(float x) {
    float y; asm("ex2.approx.f32 %0, %1;" : "=f"(y) : "f"(x)); return y;
}

// scalar-weight row vs two packed-x pairs (weights duplicated on the fly, cold path)
__device__ __forceinline__ void proj(const float* __restrict__ wrow, float bias,
                                     const ull x0[NB_D], const ull x1[NB_D],
                                     ull& o0, ull& o1) {
    float4 a = *(const float4*)(wrow);
    float4 b = *(const float4*)(wrow + 4);
    float  c = wrow[8];
    ull w[NB_D];
    w[0]=pack2(a.x,a.x); w[1]=pack2(a.y,a.y); w[2]=pack2(a.z,a.z); w[3]=pack2(a.w,a.w);
    w[4]=pack2(b.x,b.x); w[5]=pack2(b.y,b.y); w[6]=pack2(b.z,b.z); w[7]=pack2(b.w,b.w);
    w[8]=pack2(c,c);
    ull t0 = pack2(bias, bias);
    ull t1 = t0;
    #pragma unroll
    for (int d = 0; d < NB_D; ++d) {
        t0 = fma2(w[d], x0[d], t0);
        t1 = fma2(w[d], x1[d], t1);
    }
    o0 = t0; o1 = t1;
}

__global__ __launch_bounds__(64)
void bert_kernel(const int*   __restrict__ tokens,
                 const float* __restrict__ emb,
                 const float* __restrict__ Wq, const float* __restrict__ bq,
                 const float* __restrict__ Wk, const float* __restrict__ bk,
                 const float* __restrict__ Wv, const float* __restrict__ bv,
                 const float* __restrict__ Wout, const float* __restrict__ bout,
                 float* __restrict__ out)
{
    // transposed, NON-duplicated K/V tiles: one batch per warp
    __shared__ __align__(16) float sKt[2][NB_D][NB_S];   // 9216 B
    __shared__ __align__(16) float sVt[2][NB_D][NB_S];   // 9216 B
    // cold scalar weights (Wq/bq pre-scaled by QSCL)
    __shared__ __align__(16) float sW[NB_BLK][3][NB_D][RP];  // 5184 B
    __shared__ float sB[NB_BLK][3][NB_D];                    // 432 B
    __shared__ __align__(16) float sWout[NB_V][RP];
    __shared__ __align__(16) float sEmb[NB_V][RP];
    __shared__ float sBout[NB_V];
    // total ~24.6 KB

    const int tid  = threadIdx.x;
    const int w    = tid >> 5;       // warp id == batch-in-CTA
    const int lane = tid & 31;
    const int b    = blockIdx.x * 2 + w;

    // ---- cooperative weight load (Wq scaled into exp2 domain) ----
    for (int idx = tid; idx < NB_BLK * NB_D * NB_D; idx += 64) {
        int i = idx / (NB_D * NB_D);
        int r = idx % (NB_D * NB_D);
        int e = r / NB_D, d = r % NB_D;
        sW[i][0][e][d] = Wq[idx] * QSCL;
        sW[i][1][e][d] = Wk[idx];
        sW[i][2][e][d] = Wv[idx];
    }
    for (int idx = tid; idx < NB_BLK * NB_D; idx += 64) {
        int i = idx / NB_D, e = idx % NB_D;
        sB[i][0][e] = bq[idx] * QSCL;
        sB[i][1][e] = bk[idx];
        sB[i][2][e] = bv[idx];
    }
    if (tid < NB_V * NB_D) {
        sWout[tid / NB_D][tid % NB_D] = Wout[tid];
        sEmb [tid / NB_D][tid % NB_D] = emb[tid];
    }
    if (tid < NB_V) sBout[tid] = bout[tid];
    __syncthreads();

    // ---- x for 4 positions per lane: pair p = (lane+64p, lane+64p+32) ----
    ull x2[2][NB_D];
    {
        const float L2_1E4 = 13.287712379549449f;
        #pragma unroll
        for (int p = 0; p < 2; ++p) {
            int posA = lane + p * 64;
            int posB = posA + 32;
            int tokA = tokens[b * NB_S + posA];
            int tokB = tokens[b * NB_S + posB];
            #pragma unroll
            for (int d = 0; d < NB_D; ++d) {
                float ex   = (float)(2 * (d >> 1)) * (1.0f / 9.0f);
                float invf = exp2f(-ex * L2_1E4);
                float angA = (float)posA * invf;
                float angB = (float)posB * invf;
                float peA  = ((d & 1) == 0) ? sinf(angA) : cosf(angA);
                float peB  = ((d & 1) == 0) ? sinf(angB) : cosf(angB);
                x2[p][d] = pack2(sEmb[tokA][d] + peA, sEmb[tokB][d] + peB);
            }
        }
    }

    float* Kt = &sKt[w][0][0];   // [d][k] at d*128+k
    float* Vt = &sVt[w][0][0];

    #pragma unroll 1
    for (int blk = 0; blk < NB_BLK; ++blk) {
        // ---- QKV projection; K/V written TRANSPOSED (scalar, no duplication) ----
        ull q2[2][NB_D];
        #pragma unroll
        for (int e = 0; e < NB_D; ++e) {
            ull k0, k1, v0, v1;
            proj(&sW[blk][0][e][0], sB[blk][0][e], x2[0], x2[1], q2[0][e], q2[1][e]);
            proj(&sW[blk][1][e][0], sB[blk][1][e], x2[0], x2[1], k0, k1);
            proj(&sW[blk][2][e][0], sB[blk][2][e], x2[0], x2[1], v0, v1);
            float a, bb;
            unpack2(k0, a, bb);  Kt[e*NB_S + lane] = a;  Kt[e*NB_S + lane+32] = bb;
            unpack2(k1, a, bb);  Kt[e*NB_S + lane+64] = a;  Kt[e*NB_S + lane+96] = bb;
            unpack2(v0, a, bb);  Vt[e*NB_S + lane] = a;  Vt[e*NB_S + lane+32] = bb;
            unpack2(v1, a, bb);  Vt[e*NB_S + lane+64] = a;  Vt[e*NB_S + lane+96] = bb;
        }
        __syncwarp();

        // ---- two query halves per warp (2 queries/lane each) ----
        #pragma unroll
        for (int h = 0; h < 2; ++h) {
            // duplicated q in registers (free pack MOVs, alu pipe)
            ull qa[NB_D], qb[NB_D];
            #pragma unroll
            for (int d = 0; d < NB_D; ++d) {
                float a, bb; unpack2(q2[h][d], a, bb);
                qa[d] = pack2(a, a);
                qb[d] = pack2(bb, bb);
            }

            // ---- pass 1: per-query max (scores already in exp2 domain) ----
            float m0 = -1e30f, m1 = -1e30f;
            #pragma unroll 2
            for (int g = 0; g < NB_S / 4; ++g) {
                ull s00, s01, s10, s11;
                {
                    const ulonglong2 kk0 = *(const ulonglong2*)&Kt[0*NB_S + g*4];
                    s00 = mul2(kk0.x, qa[0]); s01 = mul2(kk0.y, qa[0]);
                    s10 = mul2(kk0.x, qb[0]); s11 = mul2(kk0.y, qb[0]);
                }
                #pragma unroll
                for (int d = 1; d < NB_D; ++d) {
                    const ulonglong2 kk = *(const ulonglong2*)&Kt[d*NB_S + g*4];
                    s00 = fma2(kk.x, qa[d], s00); s01 = fma2(kk.y, qa[d], s01);
                    s10 = fma2(kk.x, qb[d], s10); s11 = fma2(kk.y, qb[d], s11);
                }
                float a, bb;
                unpack2(s00, a, bb); m0 = fmaxf(m0, fmaxf(a, bb));
                unpack2(s01, a, bb); m0 = fmaxf(m0, fmaxf(a, bb));
                unpack2(s10, a, bb); m1 = fmaxf(m1, fmaxf(a, bb));
                unpack2(s11, a, bb); m1 = fmaxf(m1, fmaxf(a, bb));
            }

            // ---- pass 2: exp2-weighted V accumulation (packed over key pairs) ----
            ull acc0[NB_D], acc1[NB_D];
            #pragma unroll
            for (int d = 0; d < NB_D; ++d) { acc0[d] = 0ULL; acc1[d] = 0ULL; }
            ull den0 = 0ULL, den1 = 0ULL;

            #pragma unroll 2
            for (int g = 0; g < NB_S / 4; ++g) {
                ull s00, s01, s10, s11;
                {
                    const ulonglong2 kk0 = *(const ulonglong2*)&Kt[0*NB_S + g*4];
                    s00 = mul2(kk0.x, qa[0]); s01 = mul2(kk0.y, qa[0]);
                    s10 = mul2(kk0.x, qb[0]); s11 = mul2(kk0.y, qb[0]);
                }
                #pragma unroll
                for (int d = 1; d < NB_D; ++d) {
                    const ulonglong2 kk = *(const ulonglong2*)&Kt[d*NB_S + g*4];
                    s00 = fma2(kk.x, qa[d], s00); s01 = fma2(kk.y, qa[d], s01);
                    s10 = fma2(kk.x, qb[d], s10); s11 = fma2(kk.y, qb[d], s11);
                }
                float a, bb;
                unpack2(s00, a, bb);
                ull ep00 = pack2(ex2f(a - m0), ex2f(bb - m0));
                unpack2(s01, a, bb);
                ull ep01 = pack2(ex2f(a - m0), ex2f(bb - m0));
                unpack2(s10, a, bb);
                ull ep10 = pack2(ex2f(a - m1), ex2f(bb - m1));
                unpack2(s11, a, bb);
                ull ep11 = pack2(ex2f(a - m1), ex2f(bb - m1));
                den0 = add2(den0, ep00); den0 = add2(den0, ep01);
                den1 = add2(den1, ep10); den1 = add2(den1, ep11);
                #pragma unroll
                for (int d = 0; d < NB_D; ++d) {
                    const ulonglong2 vv = *(const ulonglong2*)&Vt[d*NB_S + g*4];
                    acc0[d] = fma2(ep00, vv.x, acc0[d]);
                    acc0[d] = fma2(ep01, vv.y, acc0[d]);
                    acc1[d] = fma2(ep10, vv.x, acc1[d]);
                    acc1[d] = fma2(ep11, vv.y, acc1[d]);
                }
            }

            float da, db;
            unpack2(den0, da, db);
            float inv0 = __fdividef(1.f, da + db);
            unpack2(den1, da, db);
            float inv1 = __fdividef(1.f, da + db);
            #pragma unroll
            for (int d = 0; d < NB_D; ++d) {
                float a0, b0, a1, b1;
                unpack2(acc0[d], a0, b0);
                unpack2(acc1[d], a1, b1);
                x2[h][d] = pack2((a0 + b0) * inv0, (a1 + b1) * inv1);
            }
        }
        __syncwarp();   // protect Kt/Vt before next block overwrites
    }

    // ---- output head: logits + log_softmax over V=5 ----
    ull lg0[NB_V], lg1[NB_V];
    #pragma unroll
    for (int v = 0; v < NB_V; ++v)
        proj(&sWout[v][0], sBout[v], x2[0], x2[1], lg0[v], lg1[v]);

    #pragma unroll
    for (int p = 0; p < 2; ++p) {
        #pragma unroll
        for (int half = 0; half < 2; ++half) {
            int pos = lane + p * 64 + half * 32;
            float lg[NB_V];
            #pragma unroll
            for (int v = 0; v < NB_V; ++v) {
                float a, bb;
                unpack2(p == 0 ? lg0[v] : lg1[v], a, bb);
                lg[v] = half == 0 ? a : bb;
            }
            float mx = lg[0];
            #pragma unroll
            for (int v = 1; v < NB_V; ++v) mx = fmaxf(mx, lg[v]);
            float sum = 0.f;
            #pragma unroll
            for (int v = 0; v < NB_V; ++v) sum += __expf(lg[v] - mx);
            float lse = mx + __logf(sum);
            float* o = out + ((size_t)b * NB_S + pos) * NB_V;
            #pragma unroll
            for (int v = 0; v < NB_V; ++v) o[v] = lg[v] - lse;
        }
    }
}

extern "C" void kernel_launch(void* const* d_in, const int* in_sizes, int n_in,
                              void* d_out, int out_size)
{
    const int*   tokens = (const int*)  d_in[0];
    const float* emb    = (const float*)d_in[1];
    const float* Wq     = (const float*)d_in[2];
    const float* bq     = (const float*)d_in[3];
    const float* Wk     = (const float*)d_in[4];
    const float* bk     = (const float*)d_in[5];
    const float* Wv     = (const float*)d_in[6];
    const float* bv     = (const float*)d_in[7];
    const float* Wout   = (const float*)d_in[8];
    const float* bout   = (const float*)d_in[9];
    float* outp = (float*)d_out;

    bert_kernel<<<NB_B / 2, 64>>>(tokens, emb, Wq, bq, Wk, bk, Wv, bv, Wout, bout, outp);
}

// round 6
// speedup vs baseline: 1.8920x; 1.3458x over previous
#include <cuda_runtime.h>

typedef unsigned long long ull;

#define NB_B   4096
#define NB_S   128
#define NB_D   9
#define NB_V   5
#define NB_BLK 4
#define RP     12

// log2(e)/3 : folds softmax scale (1/sqrt(9)) and exp->exp2 into Wq/bq
#define QSCL   0.48089834696298784f

// ---------- packed f32x2 helpers (Blackwell sm_103a) ----------
__device__ __forceinline__ ull pack2(float a, float b) {
    ull r; asm("mov.b64 %0, {%1,%2};" : "=l"(r) : "f"(a), "f"(b)); return r;
}
__device__ __forceinline__ void unpack2(ull v, float& a, float& b) {
    asm("mov.b64 {%0,%1}, %2;" : "=f"(a), "=f"(b) : "l"(v));
}
__device__ __forceinline__ ull fma2(ull a, ull b, ull c) {
    ull d; asm("fma.rn.f32x2 %0, %1, %2, %3;" : "=l"(d) : "l"(a), "l"(b), "l"(c)); return d;
}
__device__ __forceinline__ ull mul2(ull a, ull b) {
    ull d; asm("mul.rn.f32x2 %0, %1, %2;" : "=l"(d) : "l"(a), "l"(b)); return d;
}
__device__ __forceinline__ ull add2(ull a, ull b) {
    ull d; asm("add.rn.f32x2 %0, %1, %2;" : "=l"(d) : "l"(a), "l"(b)); return d;
}
__device__ __forceinline__ float ex2f(float x) {
    float y; asm("ex2.approx.f32 %0, %1;" : "=f"(y) : "f"(x)); return y;
}

// scalar-weight row vs one packed-x pair (weights duplicated on the fly, cold path)
__device__ __forceinline__ ull proj1(const float* __restrict__ wrow, float bias,
                                     const ull x[NB_D]) {
    float4 a = *(const float4*)(wrow);
    float4 b = *(const float4*)(wrow + 4);
    float  c = wrow[8];
    ull t = pack2(bias, bias);
    t = fma2(pack2(a.x,a.x), x[0], t);
    t = fma2(pack2(a.y,a.y), x[1], t);
    t = fma2(pack2(a.z,a.z), x[2], t);
    t = fma2(pack2(a.w,a.w), x[3], t);
    t = fma2(pack2(b.x,b.x), x[4], t);
    t = fma2(pack2(b.y,b.y), x[5], t);
    t = fma2(pack2(b.z,b.z), x[6], t);
    t = fma2(pack2(b.w,b.w), x[7], t);
    t = fma2(pack2(c,c),     x[8], t);
    return t;
}

__global__ __launch_bounds__(128)
void bert_kernel(const int*   __restrict__ tokens,
                 const float* __restrict__ emb,
                 const float* __restrict__ Wq, const float* __restrict__ bq,
                 const float* __restrict__ Wk, const float* __restrict__ bk,
                 const float* __restrict__ Wv, const float* __restrict__ bv,
                 const float* __restrict__ Wout, const float* __restrict__ bout,
                 float* __restrict__ out)
{
    // transposed K/V tiles, one per batch (2 batches / CTA, 2 warps / batch)
    __shared__ __align__(16) float sKt[2][NB_D][NB_S];   // 9216 B
    __shared__ __align__(16) float sVt[2][NB_D][NB_S];   // 9216 B
    __shared__ __align__(16) float sW[NB_BLK][3][NB_D][RP];
    __shared__ float sB[NB_BLK][3][NB_D];
    __shared__ __align__(16) float sWout[NB_V][RP];
    __shared__ __align__(16) float sEmb[NB_V][RP];
    __shared__ float sBout[NB_V];

    const int tid  = threadIdx.x;
    const int warp = tid >> 5;
    const int lane = tid & 31;
    const int wB   = warp >> 1;      // batch-in-CTA (0..1)
    const int wh   = warp & 1;       // query half (0..1)
    const int b    = blockIdx.x * 2 + wB;

    // ---- cooperative weight load (Wq/bq pre-scaled into exp2 domain) ----
    for (int idx = tid; idx < NB_BLK * NB_D * NB_D; idx += 128) {
        int i = idx / (NB_D * NB_D);
        int r = idx % (NB_D * NB_D);
        int e = r / NB_D, d = r % NB_D;
        sW[i][0][e][d] = Wq[idx] * QSCL;
        sW[i][1][e][d] = Wk[idx];
        sW[i][2][e][d] = Wv[idx];
    }
    for (int idx = tid; idx < NB_BLK * NB_D; idx += 128) {
        int i = idx / NB_D, e = idx % NB_D;
        sB[i][0][e] = bq[idx] * QSCL;
        sB[i][1][e] = bk[idx];
        sB[i][2][e] = bv[idx];
    }
    if (tid < NB_V * NB_D) {
        sWout[tid / NB_D][tid % NB_D] = Wout[tid];
        sEmb [tid / NB_D][tid % NB_D] = emb[tid];
    }
    if (tid < NB_V) sBout[tid] = bout[tid];
    __syncthreads();

    // ---- x for this lane's 2 positions: (posA, posB) = (wh*64+lane, +32) ----
    const int posA = wh * 64 + lane;
    const int posB = posA + 32;
    ull x2[NB_D];
    {
        const float L2_1E4 = 13.287712379549449f;
        int tokA = tokens[b * NB_S + posA];
        int tokB = tokens[b * NB_S + posB];
        #pragma unroll
        for (int d = 0; d < NB_D; ++d) {
            float ex   = (float)(2 * (d >> 1)) * (1.0f / 9.0f);
            float invf = exp2f(-ex * L2_1E4);
            float angA = (float)posA * invf;
            float angB = (float)posB * invf;
            float peA  = ((d & 1) == 0) ? sinf(angA) : cosf(angA);
            float peB  = ((d & 1) == 0) ? sinf(angB) : cosf(angB);
            x2[d] = pack2(sEmb[tokA][d] + peA, sEmb[tokB][d] + peB);
        }
    }

    float* Kt = &sKt[wB][0][0];   // [d][k] at d*128+k
    float* Vt = &sVt[wB][0][0];

    #pragma unroll 1
    for (int blk = 0; blk < NB_BLK; ++blk) {
        // ---- QKV projection; K/V written transposed ----
        ull q2[NB_D];
        #pragma unroll
        for (int e = 0; e < NB_D; ++e) {
            q2[e]  = proj1(&sW[blk][0][e][0], sB[blk][0][e], x2);
            ull kk = proj1(&sW[blk][1][e][0], sB[blk][1][e], x2);
            ull vv = proj1(&sW[blk][2][e][0], sB[blk][2][e], x2);
            float a, bb;
            unpack2(kk, a, bb);  Kt[e*NB_S + posA] = a;  Kt[e*NB_S + posB] = bb;
            unpack2(vv, a, bb);  Vt[e*NB_S + posA] = a;  Vt[e*NB_S + posB] = bb;
        }
        __syncthreads();

        // duplicated queries in registers
        ull qa[NB_D], qb[NB_D];
        #pragma unroll
        for (int d = 0; d < NB_D; ++d) {
            float a, bb; unpack2(q2[d], a, bb);
            qa[d] = pack2(a, a);
            qb[d] = pack2(bb, bb);
        }

        // ---- single-pass softmax-attention (no max: fp32 range is ample) ----
        ull acc0[NB_D], acc1[NB_D];
        #pragma unroll
        for (int d = 0; d < NB_D; ++d) { acc0[d] = 0ULL; acc1[d] = 0ULL; }
        ull den0 = 0ULL, den1 = 0ULL;

        #pragma unroll 2
        for (int g = 0; g < NB_S / 4; ++g) {
            ull s00, s01, s10, s11;
            {
                const ulonglong2 kk0 = *(const ulonglong2*)&Kt[0*NB_S + g*4];
                s00 = mul2(kk0.x, qa[0]); s01 = mul2(kk0.y, qa[0]);
                s10 = mul2(kk0.x, qb[0]); s11 = mul2(kk0.y, qb[0]);
            }
            #pragma unroll
            for (int d = 1; d < NB_D; ++d) {
                const ulonglong2 kk = *(const ulonglong2*)&Kt[d*NB_S + g*4];
                s00 = fma2(kk.x, qa[d], s00); s01 = fma2(kk.y, qa[d], s01);
                s10 = fma2(kk.x, qb[d], s10); s11 = fma2(kk.y, qb[d], s11);
            }
            float a, bb;
            unpack2(s00, a, bb);  ull ep00 = pack2(ex2f(a), ex2f(bb));
            unpack2(s01, a, bb);  ull ep01 = pack2(ex2f(a), ex2f(bb));
            unpack2(s10, a, bb);  ull ep10 = pack2(ex2f(a), ex2f(bb));
            unpack2(s11, a, bb);  ull ep11 = pack2(ex2f(a), ex2f(bb));
            den0 = add2(den0, add2(ep00, ep01));
            den1 = add2(den1, add2(ep10, ep11));
            #pragma unroll
            for (int d = 0; d < NB_D; ++d) {
                const ulonglong2 vv = *(const ulonglong2*)&Vt[d*NB_S + g*4];
                acc0[d] = fma2(ep00, vv.x, acc0[d]);
                acc0[d] = fma2(ep01, vv.y, acc0[d]);
                acc1[d] = fma2(ep10, vv.x, acc1[d]);
                acc1[d] = fma2(ep11, vv.y, acc1[d]);
            }
        }

        float da, db;
        unpack2(den0, da, db);
        float inv0 = __fdividef(1.f, da + db);
        unpack2(den1, da, db);
        float inv1 = __fdividef(1.f, da + db);
        #pragma unroll
        for (int d = 0; d < NB_D; ++d) {
            float a0, b0, a1, b1;
            unpack2(acc0[d], a0, b0);
            unpack2(acc1[d], a1, b1);
            x2[d] = pack2((a0 + b0) * inv0, (a1 + b1) * inv1);
        }
        __syncthreads();   // protect Kt/Vt before next block overwrites
    }

    // ---- output head: logits + log_softmax over V=5 (packed over posA/posB) ----
    ull lg2[NB_V];
    #pragma unroll
    for (int v = 0; v < NB_V; ++v)
        lg2[v] = proj1(&sWout[v][0], sBout[v], x2);

    #pragma unroll
    for (int half = 0; half < 2; ++half) {
        int pos = half == 0 ? posA : posB;
        float lg[NB_V];
        #pragma unroll
        for (int v = 0; v < NB_V; ++v) {
            float a, bb; unpack2(lg2[v], a, bb);
            lg[v] = half == 0 ? a : bb;
        }
        float mx = lg[0];
        #pragma unroll
        for (int v = 1; v < NB_V; ++v) mx = fmaxf(mx, lg[v]);
        float sum = 0.f;
        #pragma unroll
        for (int v = 0; v < NB_V; ++v) sum += __expf(lg[v] - mx);
        float lse = mx + __logf(sum);
        float* o = out + ((size_t)b * NB_S + pos) * NB_V;
        #pragma unroll
        for (int v = 0; v < NB_V; ++v) o[v] = lg[v] - lse;
    }
}

extern "C" void kernel_launch(void* const* d_in, const int* in_sizes, int n_in,
                              void* d_out, int out_size)
{
    const int*   tokens = (const int*)  d_in[0];
    const float* emb    = (const float*)d_in[1];
    const float* Wq     = (const float*)d_in[2];
    const float* bq     = (const float*)d_in[3];
    const float* Wk     = (const float*)d_in[4];
    const float* bk     = (const float*)d_in[5];
    const float* Wv     = (const float*)d_in[6];
    const float* bv     = (const float*)d_in[7];
    const float* Wout   = (const float*)d_in[8];
    const float* bout   = (const float*)d_in[9];
    float* outp = (float*)d_out;

    bert_kernel<<<NB_B / 2, 128>>>(tokens, emb, Wq, bq, Wk, bk, Wv, bv, Wout, bout, outp);
}